// round 15
// baseline (speedup 1.0000x reference)
#include <cuda_runtime.h>
#include <cuda_bf16.h>
#include <mma.h>
#include <cstdint>

using namespace nvcuda;

#define NUM_C 1000
#define DIM 128
#define MSZ 64
#define BATCH 64
#define LEN 512

// ---------------- device scratch (static, no runtime alloc) ----------------
__device__ __align__(16) float  g_W [NUM_C * MSZ];      // softmax(Ek@Mk^T)
__device__ __align__(16) float2 g_EA[2 * NUM_C * DIM];  // (-erase, add) per x
__device__ __align__(16) float  g_Kf[NUM_C * DIM];      // Ek @ Wf[128:256,:]
__device__ __align__(16) float  g_read0[BATCH * LEN * DIM]; // partial m 0..31
__device__ __align__(16) float  g_read1[BATCH * LEN * DIM]; // partial m 32..63
// bf16 hi/lo images of B[n][k] = Wf[k][n] (plain [n][k] layout for wmma)
__device__ __align__(16) unsigned short g_Bhi16[DIM * DIM];
__device__ __align__(16) unsigned short g_Blo16[DIM * DIM];

// ---------------- packed f32x2 helpers (scan only) ----------------
__device__ __forceinline__ void fma2(unsigned long long& d,
                                     unsigned long long a,
                                     unsigned long long b,
                                     unsigned long long c) {
    asm("fma.rn.f32x2 %0, %1, %2, %3;" : "=l"(d) : "l"(a), "l"(b), "l"(c));
}
__device__ __forceinline__ unsigned long long pack2(float lo, float hi) {
    unsigned long long r;
    asm("mov.b64 %0, {%1, %2};" : "=l"(r) : "f"(lo), "f"(hi));
    return r;
}
__device__ __forceinline__ float sum2(unsigned long long v) {
    float lo, hi;
    asm("mov.b64 {%0, %1}, %2;" : "=f"(lo), "=f"(hi) : "l"(v));
    return lo + hi;
}

// ---------------- fast transcendentals ----------------
__device__ __forceinline__ float fast_tanh(float x) {
    float xc = fminf(fmaxf(x, -15.0f), 15.0f);
    float e = __expf(2.0f * xc);
    return __fdividef(e - 1.0f, e + 1.0f);
}
__device__ __forceinline__ float fast_sigmoid(float x) {
    float xc = fminf(fmaxf(x, -30.0f), 30.0f);
    return __frcp_rn(1.0f + __expf(-xc));
}

// ============================================================================
// P: fused precompute.  grid = 251, block = 256.  (R9 version, measured 17us)
// ============================================================================
__global__ __launch_bounds__(256)
void k_pre(const float* __restrict__ Ev,
           const float* __restrict__ We, const float* __restrict__ be,
           const float* __restrict__ Wa, const float* __restrict__ ba,
           const float* __restrict__ Ek,
           const float* __restrict__ Mk,
           const float* __restrict__ Wf) {
    __shared__ float buf[12352];
    int t = threadIdx.x;

    if (blockIdx.x < 125) {
        // ---------------- erase/add branch: rows row0..row0+15 --------------
        float (*vs)[DIM]  = (float (*)[DIM])buf;
        float (*pse)[DIM] = (float (*)[DIM])(buf + 2048);
        float (*psa)[DIM] = (float (*)[DIM])(buf + 4096);
        int row0 = blockIdx.x * 16;
#pragma unroll
        for (int k = 0; k < 8; k++) {
            int idx = t + k * 256;
            vs[idx >> 7][idx & 127] = Ev[row0 * DIM + idx];
        }
        __syncthreads();

        int col = t & 127, jh = t >> 7;
        int j0 = jh * 64;
        float ae[16], aa[16];
#pragma unroll
        for (int i = 0; i < 16; i++) { ae[i] = 0.0f; aa[i] = 0.0f; }
#pragma unroll 4
        for (int jj = 0; jj < 64; jj++) {
            int j = j0 + jj;
            float we = We[j * DIM + col];
            float wa = Wa[j * DIM + col];
#pragma unroll
            for (int i = 0; i < 16; i++) {
                float v = vs[i][j];
                ae[i] = fmaf(v, we, ae[i]);
                aa[i] = fmaf(v, wa, aa[i]);
            }
        }
        if (jh == 0) {
#pragma unroll
            for (int i = 0; i < 16; i++) psa[i][col] = aa[i];
        } else {
#pragma unroll
            for (int i = 0; i < 16; i++) pse[i][col] = ae[i];
        }
        __syncthreads();
        if (jh == 0) {
            float bev = be[col];
#pragma unroll
            for (int i = 0; i < 16; i++)
                g_EA[(row0 + i) * DIM + col].x =
                    -fast_sigmoid(ae[i] + pse[i][col] + bev);
        } else {
            float bav = ba[col];
#pragma unroll
            for (int i = 0; i < 16; i++)
                g_EA[(row0 + i) * DIM + col].y =
                    fast_tanh(aa[i] + psa[i][col] + bav);
        }
    } else if (blockIdx.x < 250) {
        // ---------------- w/Kf branch: rows row0..row0+7 ----------------
        float (*Mks)[129]    = (float (*)[129])buf;
        float (*krows)[DIM]  = (float (*)[DIM])(buf + 8256);
        float (*lgp)[8][MSZ] = (float (*)[8][MSZ])(buf + 9280);
        float (*lg)[MSZ]     = (float (*)[MSZ])(buf + 10816);
        float (*psk)[DIM]    = (float (*)[DIM])(buf + 11328);
        int row0 = (blockIdx.x - 125) * 8;
#pragma unroll
        for (int k = 0; k < 4; k++) {
            int idx = t + k * 256;
            krows[idx >> 7][idx & 127] = Ek[row0 * DIM + idx];
        }
#pragma unroll 8
        for (int k = 0; k < 32; k++) {
            int idx = t + k * 256;
            Mks[idx >> 7][idx & 127] = Mk[idx];
        }
        __syncthreads();

        int col = t & 127, jh = t >> 7;
        float ak[8] = {0,0,0,0,0,0,0,0};
#pragma unroll 4
        for (int jj = 0; jj < 64; jj++) {
            int j = jh * 64 + jj;
            float wf = Wf[(DIM + j) * DIM + col];
#pragma unroll
            for (int i = 0; i < 8; i++)
                ak[i] = fmaf(krows[i][j], wf, ak[i]);
        }
        if (jh == 1) {
#pragma unroll
            for (int i = 0; i < 8; i++) psk[i][col] = ak[i];
        }

        int m = t & 63, gh = t >> 6;
        float la[8] = {0,0,0,0,0,0,0,0};
#pragma unroll 4
        for (int jj = 0; jj < 32; jj++) {
            int j = gh * 32 + jj;
            float mk = Mks[m][j];
#pragma unroll
            for (int i = 0; i < 8; i++)
                la[i] = fmaf(krows[i][j], mk, la[i]);
        }
        if (gh > 0) {
#pragma unroll
            for (int i = 0; i < 8; i++) lgp[gh - 1][i][m] = la[i];
        }
        __syncthreads();

        if (jh == 0) {
#pragma unroll
            for (int i = 0; i < 8; i++)
                g_Kf[(row0 + i) * DIM + col] = ak[i] + psk[i][col];
        }
        if (gh == 0) {
#pragma unroll
            for (int i = 0; i < 8; i++)
                lg[i][m] = la[i] + lgp[0][i][m] + lgp[1][i][m] + lgp[2][i][m];
        }
        __syncthreads();

        int row = t >> 5, l = t & 31;
        float v0 = lg[row][l], v1 = lg[row][l + 32];
        float mx = fmaxf(v0, v1);
#pragma unroll
        for (int off = 1; off < 32; off <<= 1)
            mx = fmaxf(mx, __shfl_xor_sync(0xFFFFFFFFu, mx, off));
        float e0 = __expf(v0 - mx), e1 = __expf(v1 - mx);
        float s = e0 + e1;
#pragma unroll
        for (int off = 1; off < 32; off <<= 1)
            s += __shfl_xor_sync(0xFFFFFFFFu, s, off);
        float inv = __frcp_rn(s);
        g_W[(row0 + row) * MSZ + l]      = e0 * inv;
        g_W[(row0 + row) * MSZ + l + 32] = e1 * inv;
    } else {
        // ---------------- B image branch: bf16 hi/lo, [n][k] layout ---------
        for (int idx = t; idx < DIM * DIM; idx += 256) {
            int n = idx >> 7, k = idx & 127;
            float w = Wf[k * DIM + n];
            __nv_bfloat16 h = __float2bfloat16(w);
            __nv_bfloat16 l = __float2bfloat16(w - __bfloat162float(h));
            g_Bhi16[idx] = __bfloat16_as_ushort(h);
            g_Blo16[idx] = __bfloat16_as_ushort(l);
        }
    }
}

// ============================================================================
// S: sequential memory scan.  grid = (4, 64) = 256 CTAs, block = 256.
//    R7 structure (m-split 2, d-split 2), with:
//      - DOUBLE-BUFFERED staging -> ONE __syncthreads per 16-step chunk
//      - pre-duplicated (ne2, a2) u64 pairs -> one LDS.128/step, no MOV packs
//    Thread = (dl 0..63, mg 0..3): 8 m as 4 packed f32x2 regs.
// ============================================================================
__global__ __launch_bounds__(256)
void k_scan(const int* __restrict__ q, const int* __restrict__ r,
            const float* __restrict__ Mv0) {
    int b = blockIdx.y;
    int dsplit = blockIdx.x & 1;
    int msplit = blockIdx.x >> 1;      // 0..1
    int tid = threadIdx.x;
    int dl = tid >> 2;                 // 0..63
    int mg = tid & 3;                  // 0..3
    int d = dsplit * 64 + dl;
    int m0 = msplit * 32 + mg * 8;     // 8 m per thread

    __shared__ int sq[LEN];
    __shared__ int sx[LEN];
    __shared__ __align__(16) float sh_w[2][16][32];
    __shared__ __align__(16) unsigned long long sh_ea2[2][16][64][2];

    {
        const int* qb = q + b * LEN;
        const int* rb = r + b * LEN;
        for (int i = tid; i < LEN; i += 256) {
            int qv = qb[i];
            sq[i] = qv;
            sx[i] = qv + NUM_C * rb[i];
        }
    }

    unsigned long long Mv[4];
#pragma unroll
    for (int i = 0; i < 4; i++) {
        float lo = Mv0[(m0 + 2 * i) * DIM + d];
        float hi = Mv0[(m0 + 2 * i + 1) * DIM + d];
        Mv[i] = pack2(lo, hi);
    }
    __syncthreads();   // sq/sx visible

    // staging descriptors: w 2/thread (16x32), ea 4/thread (16x64)
    int ws0[2], wm[2], es0[4], ed[4];
#pragma unroll
    for (int k = 0; k < 2; k++) {
        int idx = tid + k * 256;
        ws0[k] = idx >> 5; wm[k] = idx & 31;
    }
#pragma unroll
    for (int k = 0; k < 4; k++) {
        int idx = tid + k * 256;
        es0[k] = idx >> 6; ed[k] = idx & 63;
    }

    float rw[2];
    float2 rea[4];

    // ---- chunk 0 load ----
#pragma unroll
    for (int k = 0; k < 2; k++)
        rw[k] = g_W[sq[ws0[k]] * MSZ + msplit * 32 + wm[k]];
#pragma unroll
    for (int k = 0; k < 4; k++)
        rea[k] = g_EA[sx[es0[k]] * DIM + dsplit * 64 + ed[k]];
    // ---- commit chunk 0 to buffer 0 ----
#pragma unroll
    for (int k = 0; k < 2; k++)
        sh_w[0][ws0[k]][wm[k]] = rw[k];
#pragma unroll
    for (int k = 0; k < 4; k++) {
        ulonglong2 v;
        v.x = pack2(rea[k].x, rea[k].x);
        v.y = pack2(rea[k].y, rea[k].y);
        *(ulonglong2*)&sh_ea2[0][es0[k]][ed[k]][0] = v;
    }
    // ---- issue chunk 1 loads ----
#pragma unroll
    for (int k = 0; k < 2; k++)
        rw[k] = g_W[sq[16 + ws0[k]] * MSZ + msplit * 32 + wm[k]];
#pragma unroll
    for (int k = 0; k < 4; k++)
        rea[k] = g_EA[sx[16 + es0[k]] * DIM + dsplit * 64 + ed[k]];
    __syncthreads();

    float* gr = msplit ? g_read1 : g_read0;

    for (int c = 0; c < LEN / 16; c++) {
        int cur = c & 1;
        int t0 = c * 16;

#pragma unroll 4
        for (int s = 0; s < 16; s++) {
            ulonglong2 na = *(const ulonglong2*)&sh_ea2[cur][s][dl][0];
            const unsigned long long* wrow =
                (const unsigned long long*)&sh_w[cur][s][mg * 8];
            unsigned long long rd = 0ull, tmp;
#pragma unroll
            for (int i = 0; i < 4; i++) {
                unsigned long long w2 = wrow[i];
                fma2(rd, w2, Mv[i], rd);       // read += w * Mv_old
                fma2(tmp, na.x, Mv[i], na.y);  // tmp = a - e*Mv
                fma2(Mv[i], w2, tmp, Mv[i]);   // Mv += w*tmp
            }
            float rs = sum2(rd);
            rs += __shfl_xor_sync(0xFFFFFFFFu, rs, 1);
            rs += __shfl_xor_sync(0xFFFFFFFFu, rs, 2);
            if (mg == 0)
                gr[(b * LEN + t0 + s) * DIM + d] = rs;
        }

        if (c < LEN / 16 - 1) {
            int nxt = cur ^ 1;
            // commit chunk c+1 (loads issued last iteration; compute hid them)
#pragma unroll
            for (int k = 0; k < 2; k++)
                sh_w[nxt][ws0[k]][wm[k]] = rw[k];
#pragma unroll
            for (int k = 0; k < 4; k++) {
                ulonglong2 v;
                v.x = pack2(rea[k].x, rea[k].x);
                v.y = pack2(rea[k].y, rea[k].y);
                *(ulonglong2*)&sh_ea2[nxt][es0[k]][ed[k]][0] = v;
            }
            if (c < LEN / 16 - 2) {
                int t2 = t0 + 32;
#pragma unroll
                for (int k = 0; k < 2; k++)
                    rw[k] = g_W[sq[t2 + ws0[k]] * MSZ + msplit * 32 + wm[k]];
#pragma unroll
                for (int k = 0; k < 4; k++)
                    rea[k] = g_EA[sx[t2 + es0[k]] * DIM + dsplit * 64 + ed[k]];
            }
        }
        __syncthreads();   // buf[nxt] writes visible before next chunk reads
    }
}

// ============================================================================
// F: wmma bf16 split-precision finale (R7 verbatim, measured-best).
//    grid = 2048 (16 tokens each), block = 128 (warp w covers n [32w,32w+32)).
//    A = read (partials summed), split hi/lo bf16.  B hi/lo [n][k] -> smem.
//    3 passes: Ahi*Bhi + Ahi*Blo + Alo*Bhi, fp32 accumulators.
// ============================================================================
#define FPAD 144
#define SA_HI 0
#define SA_LO 4608
#define SB_HI 9216
#define SB_LO 46080
#define SD    82944
#define SMF_TOTAL 92160

__global__ __launch_bounds__(128)
void k_final(const int* __restrict__ q,
             const float* __restrict__ bfp,
             const float* __restrict__ Wp,
             const float* __restrict__ bp,
             float* __restrict__ out) {
    extern __shared__ char smem[];
    __nv_bfloat16* Ahi = (__nv_bfloat16*)(smem + SA_HI);
    __nv_bfloat16* Alo = (__nv_bfloat16*)(smem + SA_LO);
    __nv_bfloat16* Bhi = (__nv_bfloat16*)(smem + SB_HI);
    __nv_bfloat16* Blo = (__nv_bfloat16*)(smem + SB_LO);
    float* D = (float*)(smem + SD);
    int tid = threadIdx.x;
    int tok0 = blockIdx.x * 16;

    // stage B hi/lo (coalesced uint4)
    const uint4* srcH = (const uint4*)g_Bhi16;
    const uint4* srcL = (const uint4*)g_Blo16;
#pragma unroll
    for (int i = 0; i < 16; i++) {
        int id = tid + i * 128;        // 2048 uint4 total
        int row = id >> 4, c = id & 15;
        *(uint4*)(Bhi + row * FPAD + c * 8) = srcH[id];
        *(uint4*)(Blo + row * FPAD + c * 8) = srcL[id];
    }
    // stage A: sum partial reads, split hi/lo
    {
        int tok = tid >> 3, seg = tid & 7;
        const float4* p0 = (const float4*)(g_read0 +
                           (size_t)(tok0 + tok) * DIM + seg * 16);
        const float4* p1 = (const float4*)(g_read1 +
                           (size_t)(tok0 + tok) * DIM + seg * 16);
#pragma unroll
        for (int v = 0; v < 4; v++) {
            float4 x0 = p0[v];
            float4 x1 = p1[v];
            float xs[4] = {x0.x + x1.x, x0.y + x1.y, x0.z + x1.z, x0.w + x1.w};
#pragma unroll
            for (int e = 0; e < 4; e++) {
                int k = seg * 16 + v * 4 + e;
                float w = xs[e];
                __nv_bfloat16 h = __float2bfloat16(w);
                __nv_bfloat16 l = __float2bfloat16(w - __bfloat162float(h));
                Ahi[tok * FPAD + k] = h;
                Alo[tok * FPAD + k] = l;
            }
        }
    }
    __syncthreads();

    int wid = tid >> 5;
    int n0 = wid * 32;
    wmma::fragment<wmma::matrix_a, 16, 16, 16, __nv_bfloat16,
                   wmma::row_major> af;
    wmma::fragment<wmma::matrix_b, 16, 16, 16, __nv_bfloat16,
                   wmma::col_major> bfr;
    wmma::fragment<wmma::accumulator, 16, 16, 16, float> acc0, acc1;
    wmma::fill_fragment(acc0, 0.0f);
    wmma::fill_fragment(acc1, 0.0f);
#pragma unroll
    for (int pass = 0; pass < 3; pass++) {
        const __nv_bfloat16* A = (pass == 2) ? Alo : Ahi;
        const __nv_bfloat16* B = (pass == 1) ? Blo : Bhi;
#pragma unroll
        for (int ks = 0; ks < 8; ks++) {
            wmma::load_matrix_sync(af, A + ks * 16, FPAD);
            wmma::load_matrix_sync(bfr, B + n0 * FPAD + ks * 16, FPAD);
            wmma::mma_sync(acc0, af, bfr, acc0);
            wmma::load_matrix_sync(bfr, B + (n0 + 16) * FPAD + ks * 16, FPAD);
            wmma::mma_sync(acc1, af, bfr, acc1);
        }
    }
    wmma::store_matrix_sync(D + n0, acc0, FPAD, wmma::mem_row_major);
    wmma::store_matrix_sync(D + n0 + 16, acc1, FPAD, wmma::mem_row_major);
    __syncthreads();

    // epilogue: 8 threads per token, 16 n each, shfl-reduce
    int tok = tid >> 3, g = tid & 7;
    int qv = q[tok0 + tok];
    const float* kfr = g_Kf + qv * DIM + g * 16;
    const float* drow = D + tok * FPAD + g * 16;
    float psum = 0.0f;
#pragma unroll
    for (int j = 0; j < 16; j++) {
        float f = fast_tanh(drow[j] + kfr[j] + bfp[g * 16 + j]);
        psum = fmaf(f, Wp[g * 16 + j], psum);
    }
    psum += __shfl_xor_sync(0xFFFFFFFFu, psum, 1);
    psum += __shfl_xor_sync(0xFFFFFFFFu, psum, 2);
    psum += __shfl_xor_sync(0xFFFFFFFFu, psum, 4);
    if (g == 0) out[tok0 + tok] = fast_sigmoid(psum + bp[0]);
}

// ============================================================================
extern "C" void kernel_launch(void* const* d_in, const int* in_sizes, int n_in,
                              void* d_out, int out_size) {
    const int*   q   = (const int*)  d_in[0];
    const int*   r   = (const int*)  d_in[1];
    const float* Ek  = (const float*)d_in[2];
    const float* Ev  = (const float*)d_in[3];
    const float* Mk  = (const float*)d_in[4];
    const float* Mv0 = (const float*)d_in[5];
    const float* We  = (const float*)d_in[6];
    const float* be  = (const float*)d_in[7];
    const float* Wa  = (const float*)d_in[8];
    const float* ba  = (const float*)d_in[9];
    const float* Wf  = (const float*)d_in[10];
    const float* bf  = (const float*)d_in[11];
    const float* Wp  = (const float*)d_in[12];
    const float* bp  = (const float*)d_in[13];
    float* out = (float*)d_out;

    static int smem_set = 0;
    if (!smem_set) {
        cudaFuncSetAttribute(k_final,
                             cudaFuncAttributeMaxDynamicSharedMemorySize,
                             SMF_TOTAL);
        smem_set = 1;
    }

    k_pre<<<251, 256>>>(Ev, We, be, Wa, ba, Ek, Mk, Wf);
    dim3 gs(4, BATCH);
    k_scan<<<gs, 256>>>(q, r, Mv0);
    k_final<<<BATCH * LEN / 16, 128, SMF_TOTAL>>>(q, bf, Wp, bp, out);
}

// round 16
// speedup vs baseline: 1.6806x; 1.6806x over previous
#include <cuda_runtime.h>
#include <cuda_bf16.h>
#include <mma.h>
#include <cstdint>

using namespace nvcuda;

#define NUM_C 1000
#define DIM 128
#define MSZ 64
#define BATCH 64
#define LEN 512
#define CH 32

// ---------------- device scratch (static, no runtime alloc) ----------------
__device__ __align__(16) float  g_W [NUM_C * MSZ];      // softmax(Ek@Mk^T)
__device__ __align__(16) float2 g_EA[2 * NUM_C * DIM];  // (-erase, add) per x
__device__ __align__(16) float  g_Kf[NUM_C * DIM];      // Ek @ Wf[128:256,:]
__device__ __align__(16) float  g_read0[BATCH * LEN * DIM]; // partial m 0..31
__device__ __align__(16) float  g_read1[BATCH * LEN * DIM]; // partial m 32..63
// bf16 hi/lo images of B[n][k] = Wf[k][n] (plain [n][k] layout for wmma)
__device__ __align__(16) unsigned short g_Bhi16[DIM * DIM];
__device__ __align__(16) unsigned short g_Blo16[DIM * DIM];

// ---------------- packed f32x2 helpers (scan only) ----------------
__device__ __forceinline__ void fma2(unsigned long long& d,
                                     unsigned long long a,
                                     unsigned long long b,
                                     unsigned long long c) {
    asm("fma.rn.f32x2 %0, %1, %2, %3;" : "=l"(d) : "l"(a), "l"(b), "l"(c));
}
__device__ __forceinline__ unsigned long long pack2(float lo, float hi) {
    unsigned long long r;
    asm("mov.b64 %0, {%1, %2};" : "=l"(r) : "f"(lo), "f"(hi));
    return r;
}
__device__ __forceinline__ float sum2(unsigned long long v) {
    float lo, hi;
    asm("mov.b64 {%0, %1}, %2;" : "=f"(lo), "=f"(hi) : "l"(v));
    return lo + hi;
}

// ---------------- fast transcendentals ----------------
__device__ __forceinline__ float fast_tanh(float x) {
    float xc = fminf(fmaxf(x, -15.0f), 15.0f);
    float e = __expf(2.0f * xc);
    return __fdividef(e - 1.0f, e + 1.0f);
}
__device__ __forceinline__ float fast_sigmoid(float x) {
    float xc = fminf(fmaxf(x, -30.0f), 30.0f);
    return __frcp_rn(1.0f + __expf(-xc));
}

// ============================================================================
// P: fused precompute.  grid = 251, block = 256.  (R9 version, measured 17us)
// ============================================================================
__global__ __launch_bounds__(256)
void k_pre(const float* __restrict__ Ev,
           const float* __restrict__ We, const float* __restrict__ be,
           const float* __restrict__ Wa, const float* __restrict__ ba,
           const float* __restrict__ Ek,
           const float* __restrict__ Mk,
           const float* __restrict__ Wf) {
    __shared__ float buf[12352];
    int t = threadIdx.x;

    if (blockIdx.x < 125) {
        // ---------------- erase/add branch: rows row0..row0+15 --------------
        float (*vs)[DIM]  = (float (*)[DIM])buf;
        float (*pse)[DIM] = (float (*)[DIM])(buf + 2048);
        float (*psa)[DIM] = (float (*)[DIM])(buf + 4096);
        int row0 = blockIdx.x * 16;
#pragma unroll
        for (int k = 0; k < 8; k++) {
            int idx = t + k * 256;
            vs[idx >> 7][idx & 127] = Ev[row0 * DIM + idx];
        }
        __syncthreads();

        int col = t & 127, jh = t >> 7;
        int j0 = jh * 64;
        float ae[16], aa[16];
#pragma unroll
        for (int i = 0; i < 16; i++) { ae[i] = 0.0f; aa[i] = 0.0f; }
#pragma unroll 4
        for (int jj = 0; jj < 64; jj++) {
            int j = j0 + jj;
            float we = We[j * DIM + col];
            float wa = Wa[j * DIM + col];
#pragma unroll
            for (int i = 0; i < 16; i++) {
                float v = vs[i][j];
                ae[i] = fmaf(v, we, ae[i]);
                aa[i] = fmaf(v, wa, aa[i]);
            }
        }
        if (jh == 0) {
#pragma unroll
            for (int i = 0; i < 16; i++) psa[i][col] = aa[i];
        } else {
#pragma unroll
            for (int i = 0; i < 16; i++) pse[i][col] = ae[i];
        }
        __syncthreads();
        if (jh == 0) {
            float bev = be[col];
#pragma unroll
            for (int i = 0; i < 16; i++)
                g_EA[(row0 + i) * DIM + col].x =
                    -fast_sigmoid(ae[i] + pse[i][col] + bev);
        } else {
            float bav = ba[col];
#pragma unroll
            for (int i = 0; i < 16; i++)
                g_EA[(row0 + i) * DIM + col].y =
                    fast_tanh(aa[i] + psa[i][col] + bav);
        }
    } else if (blockIdx.x < 250) {
        // ---------------- w/Kf branch: rows row0..row0+7 ----------------
        float (*Mks)[129]    = (float (*)[129])buf;
        float (*krows)[DIM]  = (float (*)[DIM])(buf + 8256);
        float (*lgp)[8][MSZ] = (float (*)[8][MSZ])(buf + 9280);
        float (*lg)[MSZ]     = (float (*)[MSZ])(buf + 10816);
        float (*psk)[DIM]    = (float (*)[DIM])(buf + 11328);
        int row0 = (blockIdx.x - 125) * 8;
#pragma unroll
        for (int k = 0; k < 4; k++) {
            int idx = t + k * 256;
            krows[idx >> 7][idx & 127] = Ek[row0 * DIM + idx];
        }
#pragma unroll 8
        for (int k = 0; k < 32; k++) {
            int idx = t + k * 256;
            Mks[idx >> 7][idx & 127] = Mk[idx];
        }
        __syncthreads();

        int col = t & 127, jh = t >> 7;
        float ak[8] = {0,0,0,0,0,0,0,0};
#pragma unroll 4
        for (int jj = 0; jj < 64; jj++) {
            int j = jh * 64 + jj;
            float wf = Wf[(DIM + j) * DIM + col];
#pragma unroll
            for (int i = 0; i < 8; i++)
                ak[i] = fmaf(krows[i][j], wf, ak[i]);
        }
        if (jh == 1) {
#pragma unroll
            for (int i = 0; i < 8; i++) psk[i][col] = ak[i];
        }

        int m = t & 63, gh = t >> 6;
        float la[8] = {0,0,0,0,0,0,0,0};
#pragma unroll 4
        for (int jj = 0; jj < 32; jj++) {
            int j = gh * 32 + jj;
            float mk = Mks[m][j];
#pragma unroll
            for (int i = 0; i < 8; i++)
                la[i] = fmaf(krows[i][j], mk, la[i]);
        }
        if (gh > 0) {
#pragma unroll
            for (int i = 0; i < 8; i++) lgp[gh - 1][i][m] = la[i];
        }
        __syncthreads();

        if (jh == 0) {
#pragma unroll
            for (int i = 0; i < 8; i++)
                g_Kf[(row0 + i) * DIM + col] = ak[i] + psk[i][col];
        }
        if (gh == 0) {
#pragma unroll
            for (int i = 0; i < 8; i++)
                lg[i][m] = la[i] + lgp[0][i][m] + lgp[1][i][m] + lgp[2][i][m];
        }
        __syncthreads();

        int row = t >> 5, l = t & 31;
        float v0 = lg[row][l], v1 = lg[row][l + 32];
        float mx = fmaxf(v0, v1);
#pragma unroll
        for (int off = 1; off < 32; off <<= 1)
            mx = fmaxf(mx, __shfl_xor_sync(0xFFFFFFFFu, mx, off));
        float e0 = __expf(v0 - mx), e1 = __expf(v1 - mx);
        float s = e0 + e1;
#pragma unroll
        for (int off = 1; off < 32; off <<= 1)
            s += __shfl_xor_sync(0xFFFFFFFFu, s, off);
        float inv = __frcp_rn(s);
        g_W[(row0 + row) * MSZ + l]      = e0 * inv;
        g_W[(row0 + row) * MSZ + l + 32] = e1 * inv;
    } else {
        // ---------------- B image branch: bf16 hi/lo, [n][k] layout ---------
        for (int idx = t; idx < DIM * DIM; idx += 256) {
            int n = idx >> 7, k = idx & 127;
            float w = Wf[k * DIM + n];
            __nv_bfloat16 h = __float2bfloat16(w);
            __nv_bfloat16 l = __float2bfloat16(w - __bfloat162float(h));
            g_Bhi16[idx] = __bfloat16_as_ushort(h);
            g_Blo16[idx] = __bfloat16_as_ushort(l);
        }
    }
}

// ============================================================================
// S: sequential memory scan.  grid = (4, 64) = 256 CTAs, block = 256.
//    m-split 2 / d-split 2 (R7/R9 proven structure), chunk = 32 steps:
//    half the barriers of the 16-step version, double the latency-hiding
//    window per chunk.  Thread = (dl 0..63, mg 0..3): 8 m as 4 packed f32x2.
// ============================================================================
__global__ __launch_bounds__(256)
void k_scan(const int* __restrict__ q, const int* __restrict__ r,
            const float* __restrict__ Mv0) {
    int b = blockIdx.y;
    int dsplit = blockIdx.x & 1;
    int msplit = blockIdx.x >> 1;      // 0..1
    int tid = threadIdx.x;
    int dl = tid >> 2;                 // 0..63
    int mg = tid & 3;                  // 0..3
    int d = dsplit * 64 + dl;
    int m0 = msplit * 32 + mg * 8;     // 8 m per thread

    __shared__ int sq[LEN];
    __shared__ int sx[LEN];
    __shared__ __align__(16) float  sh_w [CH][32];
    __shared__ __align__(16) float2 sh_ea[CH][64];

    {
        const int* qb = q + b * LEN;
        const int* rb = r + b * LEN;
        for (int i = tid; i < LEN; i += 256) {
            int qv = qb[i];
            sq[i] = qv;
            sx[i] = qv + NUM_C * rb[i];
        }
    }

    unsigned long long Mv[4];
#pragma unroll
    for (int i = 0; i < 4; i++) {
        float lo = Mv0[(m0 + 2 * i) * DIM + d];
        float hi = Mv0[(m0 + 2 * i + 1) * DIM + d];
        Mv[i] = pack2(lo, hi);
    }
    __syncthreads();   // sq/sx visible

    // staging: w 4/thread (32x32 = 1024), ea 8/thread (32x64 = 2048 float2)
    int ws0[4], wm[4], es0[8], ed[8];
#pragma unroll
    for (int k = 0; k < 4; k++) {
        int idx = tid + k * 256;
        ws0[k] = idx >> 5; wm[k] = idx & 31;
    }
#pragma unroll
    for (int k = 0; k < 8; k++) {
        int idx = tid + k * 256;
        es0[k] = idx >> 6; ed[k] = idx & 63;
    }

    float rw[4];
    float2 rea[8];
    // prefetch chunk 0
#pragma unroll
    for (int k = 0; k < 4; k++)
        rw[k] = g_W[sq[ws0[k]] * MSZ + msplit * 32 + wm[k]];
#pragma unroll
    for (int k = 0; k < 8; k++)
        rea[k] = g_EA[sx[es0[k]] * DIM + dsplit * 64 + ed[k]];

    float* gr = msplit ? g_read1 : g_read0;

    for (int c = 0; c < LEN / CH; c++) {
        // commit staged regs to shared
#pragma unroll
        for (int k = 0; k < 4; k++)
            sh_w[ws0[k]][wm[k]] = rw[k];
#pragma unroll
        for (int k = 0; k < 8; k++)
            sh_ea[es0[k]][ed[k]] = rea[k];
        __syncthreads();

        // issue next chunk's gathers (hidden under this chunk's compute)
        if (c < LEN / CH - 1) {
            int t1 = (c + 1) * CH;
#pragma unroll
            for (int k = 0; k < 4; k++)
                rw[k] = g_W[sq[t1 + ws0[k]] * MSZ + msplit * 32 + wm[k]];
#pragma unroll
            for (int k = 0; k < 8; k++)
                rea[k] = g_EA[sx[t1 + es0[k]] * DIM + dsplit * 64 + ed[k]];
        }

        int t0 = c * CH;
#pragma unroll 4
        for (int s = 0; s < CH; s++) {
            float2 ea = sh_ea[s][dl];               // (-e, a)
            unsigned long long ne2 = pack2(ea.x, ea.x);
            unsigned long long a2  = pack2(ea.y, ea.y);
            unsigned long long rd = 0ull;
            const unsigned long long* wrow =
                (const unsigned long long*)(&sh_w[s][mg * 8]);
#pragma unroll
            for (int i = 0; i < 4; i++) {
                unsigned long long w2 = wrow[i];
                unsigned long long tmp;
                fma2(rd, w2, Mv[i], rd);       // read += w * Mv_old
                fma2(tmp, ne2, Mv[i], a2);     // tmp = a - e*Mv
                fma2(Mv[i], w2, tmp, Mv[i]);   // Mv += w*tmp
            }
            float rs = sum2(rd);
            rs += __shfl_xor_sync(0xFFFFFFFFu, rs, 1);
            rs += __shfl_xor_sync(0xFFFFFFFFu, rs, 2);
            if (mg == 0)
                gr[(b * LEN + t0 + s) * DIM + d] = rs;
        }
        __syncthreads();
    }
}

// ============================================================================
// F: wmma bf16 split-precision finale (R7/R9 verbatim, measured-best).
//    grid = 2048 (16 tokens each), block = 128 (warp w covers n [32w,32w+32)).
//    A = read (partials summed), split hi/lo bf16.  B hi/lo [n][k] -> smem.
//    3 passes: Ahi*Bhi + Ahi*Blo + Alo*Bhi, fp32 accumulators.
// ============================================================================
#define FPAD 144
#define SA_HI 0
#define SA_LO 4608
#define SB_HI 9216
#define SB_LO 46080
#define SD    82944
#define SMF_TOTAL 92160

__global__ __launch_bounds__(128)
void k_final(const int* __restrict__ q,
             const float* __restrict__ bfp,
             const float* __restrict__ Wp,
             const float* __restrict__ bp,
             float* __restrict__ out) {
    extern __shared__ char smem[];
    __nv_bfloat16* Ahi = (__nv_bfloat16*)(smem + SA_HI);
    __nv_bfloat16* Alo = (__nv_bfloat16*)(smem + SA_LO);
    __nv_bfloat16* Bhi = (__nv_bfloat16*)(smem + SB_HI);
    __nv_bfloat16* Blo = (__nv_bfloat16*)(smem + SB_LO);
    float* D = (float*)(smem + SD);
    int tid = threadIdx.x;
    int tok0 = blockIdx.x * 16;

    // stage B hi/lo (coalesced uint4)
    const uint4* srcH = (const uint4*)g_Bhi16;
    const uint4* srcL = (const uint4*)g_Blo16;
#pragma unroll
    for (int i = 0; i < 16; i++) {
        int id = tid + i * 128;        // 2048 uint4 total
        int row = id >> 4, c = id & 15;
        *(uint4*)(Bhi + row * FPAD + c * 8) = srcH[id];
        *(uint4*)(Blo + row * FPAD + c * 8) = srcL[id];
    }
    // stage A: sum partial reads, split hi/lo
    {
        int tok = tid >> 3, seg = tid & 7;
        const float4* p0 = (const float4*)(g_read0 +
                           (size_t)(tok0 + tok) * DIM + seg * 16);
        const float4* p1 = (const float4*)(g_read1 +
                           (size_t)(tok0 + tok) * DIM + seg * 16);
#pragma unroll
        for (int v = 0; v < 4; v++) {
            float4 x0 = p0[v];
            float4 x1 = p1[v];
            float xs[4] = {x0.x + x1.x, x0.y + x1.y, x0.z + x1.z, x0.w + x1.w};
#pragma unroll
            for (int e = 0; e < 4; e++) {
                int k = seg * 16 + v * 4 + e;
                float w = xs[e];
                __nv_bfloat16 h = __float2bfloat16(w);
                __nv_bfloat16 l = __float2bfloat16(w - __bfloat162float(h));
                Ahi[tok * FPAD + k] = h;
                Alo[tok * FPAD + k] = l;
            }
        }
    }
    __syncthreads();

    int wid = tid >> 5;
    int n0 = wid * 32;
    wmma::fragment<wmma::matrix_a, 16, 16, 16, __nv_bfloat16,
                   wmma::row_major> af;
    wmma::fragment<wmma::matrix_b, 16, 16, 16, __nv_bfloat16,
                   wmma::col_major> bfr;
    wmma::fragment<wmma::accumulator, 16, 16, 16, float> acc0, acc1;
    wmma::fill_fragment(acc0, 0.0f);
    wmma::fill_fragment(acc1, 0.0f);
#pragma unroll
    for (int pass = 0; pass < 3; pass++) {
        const __nv_bfloat16* A = (pass == 2) ? Alo : Ahi;
        const __nv_bfloat16* B = (pass == 1) ? Blo : Bhi;
#pragma unroll
        for (int ks = 0; ks < 8; ks++) {
            wmma::load_matrix_sync(af, A + ks * 16, FPAD);
            wmma::load_matrix_sync(bfr, B + n0 * FPAD + ks * 16, FPAD);
            wmma::mma_sync(acc0, af, bfr, acc0);
            wmma::load_matrix_sync(bfr, B + (n0 + 16) * FPAD + ks * 16, FPAD);
            wmma::mma_sync(acc1, af, bfr, acc1);
        }
    }
    wmma::store_matrix_sync(D + n0, acc0, FPAD, wmma::mem_row_major);
    wmma::store_matrix_sync(D + n0 + 16, acc1, FPAD, wmma::mem_row_major);
    __syncthreads();

    // epilogue: 8 threads per token, 16 n each, shfl-reduce
    int tok = tid >> 3, g = tid & 7;
    int qv = q[tok0 + tok];
    const float* kfr = g_Kf + qv * DIM + g * 16;
    const float* drow = D + tok * FPAD + g * 16;
    float psum = 0.0f;
#pragma unroll
    for (int j = 0; j < 16; j++) {
        float f = fast_tanh(drow[j] + kfr[j] + bfp[g * 16 + j]);
        psum = fmaf(f, Wp[g * 16 + j], psum);
    }
    psum += __shfl_xor_sync(0xFFFFFFFFu, psum, 1);
    psum += __shfl_xor_sync(0xFFFFFFFFu, psum, 2);
    psum += __shfl_xor_sync(0xFFFFFFFFu, psum, 4);
    if (g == 0) out[tok0 + tok] = fast_sigmoid(psum + bp[0]);
}

// ============================================================================
extern "C" void kernel_launch(void* const* d_in, const int* in_sizes, int n_in,
                              void* d_out, int out_size) {
    const int*   q   = (const int*)  d_in[0];
    const int*   r   = (const int*)  d_in[1];
    const float* Ek  = (const float*)d_in[2];
    const float* Ev  = (const float*)d_in[3];
    const float* Mk  = (const float*)d_in[4];
    const float* Mv0 = (const float*)d_in[5];
    const float* We  = (const float*)d_in[6];
    const float* be  = (const float*)d_in[7];
    const float* Wa  = (const float*)d_in[8];
    const float* ba  = (const float*)d_in[9];
    const float* Wf  = (const float*)d_in[10];
    const float* bf  = (const float*)d_in[11];
    const float* Wp  = (const float*)d_in[12];
    const float* bp  = (const float*)d_in[13];
    float* out = (float*)d_out;

    static int smem_set = 0;
    if (!smem_set) {
        cudaFuncSetAttribute(k_final,
                             cudaFuncAttributeMaxDynamicSharedMemorySize,
                             SMF_TOTAL);
        smem_set = 1;
    }

    k_pre<<<251, 256>>>(Ev, We, be, Wa, ba, Ek, Mk, Wf);
    dim3 gs(4, BATCH);
    k_scan<<<gs, 256>>>(q, r, Mv0);
    k_final<<<BATCH * LEN / 16, 128, SMF_TOTAL>>>(q, bf, Wp, bp, out);
}